// round 9
// baseline (speedup 1.0000x reference)
#include <cuda_runtime.h>
#include <cuda_bf16.h>
#include <cstdint>

#define BATCH 16384
#define EMBED 256
#define VOCAB 50000
#define NS    4096

// smem: A 2 k-chunks x [128r x 128 s8] XOR-swizzled = 32768
//       B 3 bufs x [128n x 128 s8] swizzled = 49152
#define OFF_A   0
#define OFF_B   32768
#define OFF_RED 81920        // 128 floats scale scratch / 256 floats reduce
#define SMEM_TOTAL 82944
#define NCH 32               // (NS/2)/128 n-tiles * 2 k-chunks

// ---------------- device scratch ----------------
__device__ __align__(16) uint8_t g_Bw8[NS * EMBED];  // gathered sampled weights, s8
__device__ float g_cb[NS * 2];                       // per col: {sB, bias - log(ec)}
__device__ float g_ps[2][BATCH];
__device__ float g_true[BATCH];

__device__ __forceinline__ float neg_log_ec(float fid) {
    const float inv_logv = 1.0f / logf((float)VOCAB + 1.0f);
    float p  = (logf(fid + 2.0f) - logf(fid + 1.0f)) * inv_logv;
    float ec = -expm1f((float)NS * log1pf(-p));
    return -logf(ec);
}

__device__ __forceinline__ unsigned su32(const void* p) {
    return (unsigned)__cvta_generic_to_shared(p);
}

__device__ __forceinline__ float absmax8(float4 a, float4 b) {
    float m = fmaxf(fmaxf(fmaxf(fabsf(a.x), fabsf(a.y)), fmaxf(fabsf(a.z), fabsf(a.w))),
                    fmaxf(fmaxf(fabsf(b.x), fabsf(b.y)), fmaxf(fabsf(b.z), fabsf(b.w))));
    #pragma unroll
    for (int off = 16; off > 0; off >>= 1)
        m = fmaxf(m, __shfl_xor_sync(0xffffffffu, m, off));
    return fmaxf(m, 1e-30f);
}

__device__ __forceinline__ uint2 quant8(float4 a, float4 b, float inv) {
    int b0 = __float2int_rn(a.x * inv), b1 = __float2int_rn(a.y * inv);
    int b2 = __float2int_rn(a.z * inv), b3 = __float2int_rn(a.w * inv);
    int b4 = __float2int_rn(b.x * inv), b5 = __float2int_rn(b.y * inv);
    int b6 = __float2int_rn(b.z * inv), b7 = __float2int_rn(b.w * inv);
    uint2 r;
    r.x = (b0 & 0xff) | ((b1 & 0xff) << 8) | ((b2 & 0xff) << 16) | ((unsigned)(b3 & 0xff) << 24);
    r.y = (b4 & 0xff) | ((b5 & 0xff) << 8) | ((b6 & 0xff) << 16) | ((unsigned)(b7 & 0xff) << 24);
    return r;
}

// ---------------- fused prep ----------------
// blocks [0,512): gather sampled W rows -> s8 + {scale, offset} (1 warp/row)
// blocks [512,1024): true logits (fp32, 4 rows per warp)
__global__ void k_pre(const int* __restrict__ sids, const float* __restrict__ W,
                      const float* __restrict__ bias, const float* __restrict__ emb,
                      const int* __restrict__ tgt) {
    const int b    = blockIdx.x;
    const int tid  = threadIdx.x;
    const int w    = tid >> 5;
    const int lane = tid & 31;
    if (b < 512) {
        int s  = b * 8 + w;
        int id = sids[s];
        const float4* src = (const float4*)(W + (size_t)id * EMBED + lane * 8);
        float4 v0 = src[0], v1 = src[1];
        float am  = absmax8(v0, v1);
        float inv = 127.0f / am;
        *(uint2*)(g_Bw8 + (size_t)s * EMBED + lane * 8) = quant8(v0, v1, inv);
        if (lane == 0) {
            g_cb[2 * s]     = am * (1.0f / 127.0f);
            g_cb[2 * s + 1] = bias[id] + neg_log_ec((float)id);
        }
    } else {
        const int tb = b - 512;
        const int r0 = (tb * 8 + w) * 4;
        int ids[4];
        #pragma unroll
        for (int j = 0; j < 4; j++) ids[j] = tgt[r0 + j];
        float s[4];
        #pragma unroll
        for (int j = 0; j < 4; j++) {
            const float4* e4 = (const float4*)(emb + (size_t)(r0 + j) * EMBED);
            const float4* w4 = (const float4*)(W + (size_t)ids[j] * EMBED);
            float4 a0 = e4[lane], a1 = e4[lane + 32];
            float4 b0 = w4[lane], b1 = w4[lane + 32];
            s[j] = a0.x*b0.x + a0.y*b0.y + a0.z*b0.z + a0.w*b0.w
                 + a1.x*b1.x + a1.y*b1.y + a1.z*b1.z + a1.w*b1.w;
        }
        #pragma unroll
        for (int off = 16; off > 0; off >>= 1)
            #pragma unroll
            for (int j = 0; j < 4; j++)
                s[j] += __shfl_xor_sync(0xffffffffu, s[j], off);
        if (lane == 0) {
            #pragma unroll
            for (int j = 0; j < 4; j++) {
                float tl = s[j] + bias[ids[j]] + neg_log_ec((float)ids[j]);
                g_true[r0 + j] = fmaxf(tl, 0.f) - tl + log1pf(expf(-fabsf(tl)));
            }
        }
    }
}

// ---------------- fused INT8 GEMM + softplus row-sum ----------------
// grid 256 = 128 M-tiles x 2 N-halves. 8 warps: 4M(32) x 2N(64). BN=128.
// mma.sync.m16n8k32 s8; per-row absmax scales; 3-stage B ring; A-frag dbuf.
__global__ __launch_bounds__(256, 2) void k_gemm(const float* __restrict__ emb) {
    extern __shared__ __align__(16) char smp[];
    const uint32_t base = su32(smp);
    float* red = (float*)(smp + OFF_RED);

    const int tid  = threadIdx.x;
    const int lane = tid & 31;
    const int warp = tid >> 5;
    const int wm   = warp & 3;   // 32-row group
    const int wn   = warp >> 2;  // 64-col group
    const int mb   = blockIdx.x >> 1;
    const int half = blockIdx.x & 1;
    const int m0   = mb * 128;
    const int nb0  = half * (NS / 2);

    // ---- B chunk loader: ch=(nt,kb) -> buf ch%3, 128n x 128 s8 swizzled ----
    auto loadB = [&](int ch) {
        const int nt = ch >> 1, kb = ch & 1, b = ch % 3;
        const uint8_t* sb = g_Bw8 + (size_t)(nb0 + nt * 128) * EMBED + kb * 128;
        #pragma unroll
        for (int it = 0; it < 4; it++) {
            int q = tid + it * 256;
            int n = q >> 3, g = q & 7;
            uint32_t dst = base + OFF_B + b * 16384 + n * 128 + (((g ^ n) & 7) << 4);
            const void* src = sb + (size_t)n * EMBED + g * 16;
            asm volatile("cp.async.cg.shared.global [%0], [%1], 16;" :: "r"(dst), "l"(src));
        }
        asm volatile("cp.async.commit_group;");
    };

    loadB(0);
    loadB(1);

    // ---- A: per-row absmax quantize to s8, swizzled store (warp per row) ----
    #pragma unroll 2
    for (int rr = 0; rr < 16; rr++) {
        int r = warp * 16 + rr;
        const float4* e4 = (const float4*)(emb + (size_t)(m0 + r) * EMBED + lane * 8);
        float4 v0 = e4[0], v1 = e4[1];
        float am  = absmax8(v0, v1);
        float inv = 127.0f / am;
        uint32_t addr = (uint32_t)(OFF_A + (lane >> 4) * 16384 + r * 128
                        + (((((lane & 15) >> 1) ^ r) & 7) << 4) + (lane & 1) * 8);
        *(uint2*)(smp + addr) = quant8(v0, v1, inv);
        if (lane == 0) red[r] = am * (1.0f / 127.0f);
    }
    __syncthreads();
    float sA[4];
    #pragma unroll
    for (int s = 0; s < 4; s++)
        sA[s] = red[wm * 32 + (s >> 1) * 16 + (s & 1) * 8 + (lane >> 2)];

    int acc[2][8][4];
    #pragma unroll
    for (int mi = 0; mi < 2; mi++)
        #pragma unroll
        for (int ni = 0; ni < 8; ni++)
            #pragma unroll
            for (int q = 0; q < 4; q++) acc[mi][ni][q] = 0;
    float rs[4] = {0.f, 0.f, 0.f, 0.f};

    // ---- fragment loaders (b16-unit view of s8 pairs) ----
    auto ldA = [&](unsigned (&a)[2][4], uint32_t abase, int ki) {
        #pragma unroll
        for (int mi = 0; mi < 2; mi++) {
            int rr = wm * 32 + mi * 16 + (lane & 15);
            int gp = 2 * ki + (lane >> 4);
            unsigned addr = abase + rr * 128 + (((gp ^ rr) & 7) << 4);
            asm volatile("ldmatrix.sync.aligned.m8n8.x4.shared.b16 {%0,%1,%2,%3}, [%4];\n"
                : "=r"(a[mi][0]), "=r"(a[mi][1]), "=r"(a[mi][2]), "=r"(a[mi][3])
                : "r"(addr));
        }
    };
    auto ldBf = [&](unsigned (&b)[8][2], uint32_t bbase, int ki) {
        #pragma unroll
        for (int np = 0; np < 4; np++) {
            int nn = wn * 64 + np * 16 + ((lane >> 4) << 3) + (lane & 7);
            int gp = 2 * ki + ((lane >> 3) & 1);
            unsigned addr = bbase + nn * 128 + (((gp ^ nn) & 7) << 4);
            asm volatile("ldmatrix.sync.aligned.m8n8.x4.shared.b16 {%0,%1,%2,%3}, [%4];\n"
                : "=r"(b[np * 2][0]), "=r"(b[np * 2][1]),
                  "=r"(b[np * 2 + 1][0]), "=r"(b[np * 2 + 1][1])
                : "r"(addr));
        }
    };

    for (int ch = 0; ch < NCH; ch++) {
        if (ch < NCH - 1) asm volatile("cp.async.wait_group 1;");
        else              asm volatile("cp.async.wait_group 0;");
        __syncthreads();
        if (ch + 2 < NCH) loadB(ch + 2);

        const int kb = ch & 1;
        const uint32_t abase = base + OFF_A + kb * 16384;
        const uint32_t bbase = base + OFF_B + (ch % 3) * 16384;

        unsigned aF[2][2][4];
        unsigned bF[8][2];
        ldA(aF[0], abase, 0);

        #pragma unroll
        for (int ki = 0; ki < 4; ki++) {
            ldBf(bF, bbase, ki);
            if (ki < 3) ldA(aF[(ki + 1) & 1], abase, ki + 1);
            unsigned (&a)[2][4] = aF[ki & 1];
            #pragma unroll
            for (int mi = 0; mi < 2; mi++)
                #pragma unroll
                for (int ni = 0; ni < 8; ni++)
                    asm volatile(
                        "mma.sync.aligned.m16n8k32.row.col.s32.s8.s8.s32 "
                        "{%0,%1,%2,%3},{%4,%5,%6,%7},{%8,%9},{%0,%1,%2,%3};\n"
                        : "+r"(acc[mi][ni][0]), "+r"(acc[mi][ni][1]),
                          "+r"(acc[mi][ni][2]), "+r"(acc[mi][ni][3])
                        : "r"(a[mi][0]), "r"(a[mi][1]), "r"(a[mi][2]), "r"(a[mi][3]),
                          "r"(bF[ni][0]), "r"(bF[ni][1]));
        }

        if (kb == 1) {
            const int nt = ch >> 1;
            const float* cb = g_cb + 2 * (nb0 + nt * 128 + wn * 64 + (lane & 3) * 2);
            #pragma unroll
            for (int mi = 0; mi < 2; mi++) {
                const float sa0 = sA[mi * 2], sa1 = sA[mi * 2 + 1];
                float lin0 = 0.f, lin1 = 0.f, pr0 = 1.f, pr1 = 1.f;
                #pragma unroll
                for (int ni = 0; ni < 8; ni++) {
                    float4 q = *(const float4*)(cb + ni * 16);   // {sB0,c0,sB1,c1}
                    float l0 = fmaf((float)acc[mi][ni][0] * sa0, q.x, q.y);
                    float l1 = fmaf((float)acc[mi][ni][1] * sa0, q.z, q.w);
                    float l2 = fmaf((float)acc[mi][ni][2] * sa1, q.x, q.y);
                    float l3 = fmaf((float)acc[mi][ni][3] * sa1, q.z, q.w);
                    lin0 += fmaxf(l0, 0.f) + fmaxf(l1, 0.f);
                    lin1 += fmaxf(l2, 0.f) + fmaxf(l3, 0.f);
                    pr0 *= (1.f + __expf(-fabsf(l0))) * (1.f + __expf(-fabsf(l1)));
                    pr1 *= (1.f + __expf(-fabsf(l2))) * (1.f + __expf(-fabsf(l3)));
                    acc[mi][ni][0] = 0; acc[mi][ni][1] = 0;
                    acc[mi][ni][2] = 0; acc[mi][ni][3] = 0;
                }
                rs[mi * 2 + 0] += lin0 + __logf(pr0);
                rs[mi * 2 + 1] += lin1 + __logf(pr1);
            }
        }
    }

    // ---- row-sum reduction ----
    #pragma unroll
    for (int s = 0; s < 4; s++) {
        rs[s] += __shfl_xor_sync(0xffffffffu, rs[s], 1);
        rs[s] += __shfl_xor_sync(0xffffffffu, rs[s], 2);
    }
    __syncthreads();
    if ((lane & 3) == 0) {
        #pragma unroll
        for (int s = 0; s < 4; s++) {
            int mi = s >> 1, hi = s & 1;
            int row = wm * 32 + mi * 16 + hi * 8 + (lane >> 2);
            red[wn * 128 + row] = rs[s];
        }
    }
    __syncthreads();
    if (tid < 128)
        g_ps[half][m0 + tid] = red[tid] + red[128 + tid];
}

// ---------------- final mean: 1024 threads, vectorized ----------------
__global__ void k_final(float* __restrict__ out) {
    __shared__ double redd[1024];
    const int tid = threadIdx.x;
    float s = 0.0f;
    const float4* p0 = (const float4*)g_ps[0];
    const float4* p1 = (const float4*)g_ps[1];
    const float4* p2 = (const float4*)g_true;
    #pragma unroll
    for (int i = 0; i < BATCH / 4 / 1024; i++) {
        int idx = tid + i * 1024;
        float4 a = p0[idx], b = p1[idx], c = p2[idx];
        s += a.x + a.y + a.z + a.w + b.x + b.y + b.z + b.w
           + c.x + c.y + c.z + c.w;
    }
    redd[tid] = (double)s;
    __syncthreads();
    for (int st = 512; st > 0; st >>= 1) {
        if (tid < st) redd[tid] += redd[tid + st];
        __syncthreads();
    }
    if (tid == 0) out[0] = (float)(redd[0] / (double)BATCH);
}

// ---------------- launch ----------------
extern "C" void kernel_launch(void* const* d_in, const int* in_sizes, int n_in,
                              void* d_out, int out_size) {
    const float* emb  = (const float*)d_in[0];
    const int*   tgt  = (const int*)d_in[1];
    const int*   sids = (const int*)d_in[2];
    const float* W    = (const float*)d_in[3];
    const float* bias = (const float*)d_in[4];
    float*       out  = (float*)d_out;

    cudaFuncSetAttribute(k_gemm, cudaFuncAttributeMaxDynamicSharedMemorySize, SMEM_TOTAL);

    k_pre<<<1024, 256>>>(sids, W, bias, emb, tgt);
    k_gemm<<<256, 256, SMEM_TOTAL>>>(emb);
    k_final<<<1, 1024>>>(out);
}

// round 10
// speedup vs baseline: 2.4710x; 2.4710x over previous
#include <cuda_runtime.h>
#include <cuda_bf16.h>
#include <cstdint>

#define BATCH 16384
#define EMBED 256
#define NS    4096
#define VOCAB 50000

// smem: A 4 k-chunks x [128r x 64k bf16] XOR-swizzled = 65536
//       B 3 bufs x [128n x 64k bf16] swizzled = 49152
#define OFF_A   0
#define OFF_B   65536
#define OFF_RED 114688
#define SMEM_TOTAL 115712
#define NCH 64     // (NS/2)/128 n-tiles * 4 k-chunks
#define GEMM_CTAS 256
#define TRUE_CTAS 40
#define TRUE_WARPS (TRUE_CTAS * 8)

// ---------------- device scratch ----------------
__device__ __align__(16) __nv_bfloat16 g_Bw[NS * EMBED];
__device__ float g_c[NS];
__device__ float g_ps[2][BATCH];
__device__ float g_true[BATCH];

__device__ __forceinline__ float neg_log_ec(float fid) {
    const float inv_logv = 1.0f / logf((float)VOCAB + 1.0f);
    float p  = (logf(fid + 2.0f) - logf(fid + 1.0f)) * inv_logv;
    float ec = -expm1f((float)NS * log1pf(-p));
    return -logf(ec);
}

__device__ __forceinline__ unsigned su32(const void* p) {
    return (unsigned)__cvta_generic_to_shared(p);
}

// ---------------- prep: gather B (bf16) + offsets c ----------------
__global__ void k_pre(const int* __restrict__ sids, const float* __restrict__ W,
                      const float* __restrict__ bias) {
    const int b   = blockIdx.x;
    const int tid = threadIdx.x;
    if (b < 512) {
        int i  = b * 256 + tid;
        int s  = i >> 5;
        int d8 = (i & 31) << 3;
        int id = sids[s];
        const float4* src = (const float4*)(W + (size_t)id * EMBED + d8);
        float4 x = src[0], y = src[1];
        __align__(16) __nv_bfloat162 p[4];
        p[0] = __floats2bfloat162_rn(x.x, x.y);
        p[1] = __floats2bfloat162_rn(x.z, x.w);
        p[2] = __floats2bfloat162_rn(y.x, y.y);
        p[3] = __floats2bfloat162_rn(y.z, y.w);
        *(uint4*)(g_Bw + (size_t)s * EMBED + d8) = *(const uint4*)p;
    } else {
        int s  = (b - 512) * 256 + tid;
        int id = sids[s];
        g_c[s] = bias[id] + neg_log_ec((float)id);
    }
}

// ---------------- fused GEMM + softplus + shadow true-logits ----------------
// grid 296 = 256 GEMM CTAs (128 M-tiles x 2 N-halves) + 40 true-logit CTAs
// filling the otherwise-idle occupancy slots (148 SMs x 2 CTAs).
__global__ __launch_bounds__(256, 2) void k_gemm(
    const float* __restrict__ emb, const int* __restrict__ tgt,
    const float* __restrict__ W, const float* __restrict__ bias) {
    extern __shared__ __align__(16) char smp[];

    const int tid  = threadIdx.x;
    const int lane = tid & 31;
    const int warp = tid >> 5;

    // ---- shadow CTAs: true logits, hidden under the GEMM ----
    if (blockIdx.x >= GEMM_CTAS) {
        const int gw = (blockIdx.x - GEMM_CTAS) * 8 + warp;   // 0..319
        for (int r0 = gw * 4; r0 < BATCH; r0 += TRUE_WARPS * 4) {
            int ids[4];
            #pragma unroll
            for (int j = 0; j < 4; j++) ids[j] = tgt[r0 + j];
            float s[4];
            #pragma unroll
            for (int j = 0; j < 4; j++) {
                const float4* e4 = (const float4*)(emb + (size_t)(r0 + j) * EMBED);
                const float4* w4 = (const float4*)(W + (size_t)ids[j] * EMBED);
                float4 a0 = e4[lane], a1 = e4[lane + 32];
                float4 b0 = w4[lane], b1 = w4[lane + 32];
                s[j] = a0.x*b0.x + a0.y*b0.y + a0.z*b0.z + a0.w*b0.w
                     + a1.x*b1.x + a1.y*b1.y + a1.z*b1.z + a1.w*b1.w;
            }
            #pragma unroll
            for (int off = 16; off > 0; off >>= 1)
                #pragma unroll
                for (int j = 0; j < 4; j++)
                    s[j] += __shfl_xor_sync(0xffffffffu, s[j], off);
            if (lane == 0) {
                #pragma unroll
                for (int j = 0; j < 4; j++) {
                    float tl = s[j] + bias[ids[j]] + neg_log_ec((float)ids[j]);
                    g_true[r0 + j] = fmaxf(tl, 0.f) - tl + log1pf(expf(-fabsf(tl)));
                }
            }
        }
        return;
    }

    // ---- GEMM CTAs (round-7 proven path) ----
    const uint32_t base = su32(smp);
    float* red = (float*)(smp + OFF_RED);
    const int wm   = warp & 3;   // 32-row group
    const int wn   = warp >> 2;  // 64-col group
    const int mb   = blockIdx.x >> 1;
    const int half = blockIdx.x & 1;
    const int m0   = mb * 128;
    const int nb0  = half * (NS / 2);

    auto loadB = [&](int ch) {
        const int nt = ch >> 2, kb = ch & 3, b = ch % 3;
        const __nv_bfloat16* sb = g_Bw + (size_t)(nb0 + nt * 128) * EMBED + kb * 64;
        #pragma unroll
        for (int it = 0; it < 4; it++) {
            int q = tid + it * 256;
            int n = q >> 3, g = q & 7;
            uint32_t dst = base + OFF_B + b * 16384 + n * 128 + (((g ^ n) & 7) << 4);
            const void* src = sb + (size_t)n * EMBED + g * 8;
            asm volatile("cp.async.cg.shared.global [%0], [%1], 16;" :: "r"(dst), "l"(src));
        }
        asm volatile("cp.async.commit_group;");
    };

    loadB(0);
    loadB(1);

    #pragma unroll 4
    for (int it = 0; it < 16; it++) {
        int idx = tid + it * 256;
        int r = idx >> 5, G = idx & 31;
        int c = G >> 3, g = G & 7;
        const float4* s = (const float4*)(emb + (size_t)(m0 + r) * EMBED + G * 8);
        float4 x = s[0], y = s[1];
        __align__(16) __nv_bfloat162 p[4];
        p[0] = __floats2bfloat162_rn(x.x, x.y);
        p[1] = __floats2bfloat162_rn(x.z, x.w);
        p[2] = __floats2bfloat162_rn(y.x, y.y);
        p[3] = __floats2bfloat162_rn(y.z, y.w);
        *(uint4*)(smp + OFF_A + c * 16384 + r * 128 + (((g ^ r) & 7) << 4)) = *(const uint4*)p;
    }

    float acc[2][8][4];
    #pragma unroll
    for (int mi = 0; mi < 2; mi++)
        #pragma unroll
        for (int ni = 0; ni < 8; ni++)
            #pragma unroll
            for (int q = 0; q < 4; q++) acc[mi][ni][q] = 0.0f;
    float rs[4] = {0.f, 0.f, 0.f, 0.f};

    auto ldA = [&](unsigned (&a)[2][4], uint32_t abase, int kk) {
        #pragma unroll
        for (int mi = 0; mi < 2; mi++) {
            int rr = wm * 32 + mi * 16 + (lane & 15);
            int gp = (kk >> 3) + (lane >> 4);
            unsigned addr = abase + rr * 128 + (((gp ^ rr) & 7) << 4);
            asm volatile("ldmatrix.sync.aligned.m8n8.x4.shared.b16 {%0,%1,%2,%3}, [%4];\n"
                : "=r"(a[mi][0]), "=r"(a[mi][1]), "=r"(a[mi][2]), "=r"(a[mi][3])
                : "r"(addr));
        }
    };
    auto ldBf = [&](unsigned (&b)[8][2], uint32_t bbase, int kk) {
        #pragma unroll
        for (int np = 0; np < 4; np++) {
            int nn = wn * 64 + np * 16 + ((lane >> 4) << 3) + (lane & 7);
            int gp = (kk >> 3) + ((lane >> 3) & 1);
            unsigned addr = bbase + nn * 128 + (((gp ^ nn) & 7) << 4);
            asm volatile("ldmatrix.sync.aligned.m8n8.x4.shared.b16 {%0,%1,%2,%3}, [%4];\n"
                : "=r"(b[np * 2][0]), "=r"(b[np * 2][1]),
                  "=r"(b[np * 2 + 1][0]), "=r"(b[np * 2 + 1][1])
                : "r"(addr));
        }
    };

    for (int ch = 0; ch < NCH; ch++) {
        if (ch < NCH - 1) asm volatile("cp.async.wait_group 1;");
        else              asm volatile("cp.async.wait_group 0;");
        __syncthreads();
        if (ch + 2 < NCH) loadB(ch + 2);

        const int kb = ch & 3;
        const uint32_t abase = base + OFF_A + kb * 16384;
        const uint32_t bbase = base + OFF_B + (ch % 3) * 16384;

        unsigned aF[2][2][4];
        unsigned bF[8][2];
        ldA(aF[0], abase, 0);

        #pragma unroll
        for (int ki = 0; ki < 4; ki++) {
            ldBf(bF, bbase, ki * 16);
            if (ki < 3) ldA(aF[(ki + 1) & 1], abase, (ki + 1) * 16);
            unsigned (&a)[2][4] = aF[ki & 1];
            #pragma unroll
            for (int mi = 0; mi < 2; mi++)
                #pragma unroll
                for (int ni = 0; ni < 8; ni++)
                    asm volatile(
                        "mma.sync.aligned.m16n8k16.row.col.f32.bf16.bf16.f32 "
                        "{%0,%1,%2,%3},{%4,%5,%6,%7},{%8,%9},{%0,%1,%2,%3};\n"
                        : "+f"(acc[mi][ni][0]), "+f"(acc[mi][ni][1]),
                          "+f"(acc[mi][ni][2]), "+f"(acc[mi][ni][3])
                        : "r"(a[mi][0]), "r"(a[mi][1]), "r"(a[mi][2]), "r"(a[mi][3]),
                          "r"(bF[ni][0]), "r"(bF[ni][1]));
        }

        if (kb == 3) {
            const int nt = ch >> 2;
            const float* cp = g_c + nb0 + nt * 128 + wn * 64 + (lane & 3) * 2;
            #pragma unroll
            for (int mi = 0; mi < 2; mi++) {
                float lin0 = 0.f, lin1 = 0.f, pr0 = 1.f, pr1 = 1.f;
                #pragma unroll
                for (int ni = 0; ni < 8; ni++) {
                    float2 cf = *(const float2*)(cp + ni * 8);
                    float l0 = acc[mi][ni][0] + cf.x;
                    float l1 = acc[mi][ni][1] + cf.y;
                    float l2 = acc[mi][ni][2] + cf.x;
                    float l3 = acc[mi][ni][3] + cf.y;
                    lin0 += fmaxf(l0, 0.f) + fmaxf(l1, 0.f);
                    lin1 += fmaxf(l2, 0.f) + fmaxf(l3, 0.f);
                    pr0 *= (1.f + __expf(-fabsf(l0))) * (1.f + __expf(-fabsf(l1)));
                    pr1 *= (1.f + __expf(-fabsf(l2))) * (1.f + __expf(-fabsf(l3)));
                    acc[mi][ni][0] = 0.f; acc[mi][ni][1] = 0.f;
                    acc[mi][ni][2] = 0.f; acc[mi][ni][3] = 0.f;
                }
                rs[mi * 2 + 0] += lin0 + __logf(pr0);
                rs[mi * 2 + 1] += lin1 + __logf(pr1);
            }
        }
    }

    // ---- row-sum reduction ----
    #pragma unroll
    for (int s = 0; s < 4; s++) {
        rs[s] += __shfl_xor_sync(0xffffffffu, rs[s], 1);
        rs[s] += __shfl_xor_sync(0xffffffffu, rs[s], 2);
    }
    __syncthreads();
    if ((lane & 3) == 0) {
        #pragma unroll
        for (int s = 0; s < 4; s++) {
            int mi = s >> 1, hi = s & 1;
            int row = wm * 32 + mi * 16 + hi * 8 + (lane >> 2);
            red[wn * 128 + row] = rs[s];
        }
    }
    __syncthreads();
    if (tid < 128)
        g_ps[half][m0 + tid] = red[tid] + red[128 + tid];
}

// ---------------- final mean: 1024 threads, vectorized ----------------
__global__ void k_final(float* __restrict__ out) {
    __shared__ double redd[1024];
    const int tid = threadIdx.x;
    float s = 0.0f;
    const float4* p0 = (const float4*)g_ps[0];
    const float4* p1 = (const float4*)g_ps[1];
    const float4* p2 = (const float4*)g_true;
    #pragma unroll
    for (int i = 0; i < BATCH / 4 / 1024; i++) {
        int idx = tid + i * 1024;
        float4 a = p0[idx], b = p1[idx], c = p2[idx];
        s += a.x + a.y + a.z + a.w + b.x + b.y + b.z + b.w
           + c.x + c.y + c.z + c.w;
    }
    redd[tid] = (double)s;
    __syncthreads();
    for (int st = 512; st > 0; st >>= 1) {
        if (tid < st) redd[tid] += redd[tid + st];
        __syncthreads();
    }
    if (tid == 0) out[0] = (float)(redd[0] / (double)BATCH);
}

// ---------------- launch ----------------
extern "C" void kernel_launch(void* const* d_in, const int* in_sizes, int n_in,
                              void* d_out, int out_size) {
    const float* emb  = (const float*)d_in[0];
    const int*   tgt  = (const int*)d_in[1];
    const int*   sids = (const int*)d_in[2];
    const float* W    = (const float*)d_in[3];
    const float* bias = (const float*)d_in[4];
    float*       out  = (float*)d_out;

    cudaFuncSetAttribute(k_gemm, cudaFuncAttributeMaxDynamicSharedMemorySize, SMEM_TOTAL);

    k_pre<<<528, 256>>>(sids, W, bias);
    k_gemm<<<GEMM_CTAS + TRUE_CTAS, 256, SMEM_TOTAL>>>(emb, tgt, W, bias);
    k_final<<<1, 1024>>>(out);
}